// round 6
// baseline (speedup 1.0000x reference)
#include <cuda_runtime.h>
#include <stdint.h>

#define BATCH 128
#define NQ    2000
#define NC    3
#define QC    6000
#define HALF  3000
#define HV4   750           // HALF/4
#define TOPK  100
#define NP    20
#define NPQ   (NP * 2 / 4)
#define NT1   256
#define NJ4   3             // ceil(HV4/NT1)
#define NBINS 4096
#define BPT   16            // NBINS/NT1
#define HCAP  512           // per-half candidate cap
#define NT2   256
#define CAND_CAP 1024

// Output layout (float32, reference tuple order, flattened):
#define OFF_BOXES  0
#define OFF_SCORES 51200
#define OFF_LABELS 64000
#define OFF_PTS    76800
#define OFF_MASK   588800

// global scratch (static: no allocation)
__device__ unsigned long long g_cand[BATCH * 2][HCAP];
__device__ int                g_cnt[BATCH * 2];

// ---------------- Kernel 1: per-half candidate selection ----------------
__global__ __launch_bounds__(NT1, 2)
void k1_select(const float* __restrict__ cls)
{
    __shared__ unsigned int       hist[NBINS];        // 16 KB
    __shared__ unsigned long long cand[HCAP];         // 4 KB
    __shared__ int                n_cand;
    __shared__ unsigned int       warp_tot[NT1 / 32];
    __shared__ int                sh_bcut;

    const int bid  = blockIdx.x;            // 0..255
    const int b    = bid >> 1;
    const int half = bid & 1;
    const int t    = threadIdx.x;
    const int wid  = t >> 5;
    const int lane = t & 31;

    for (int i = t; i < NBINS; i += NT1) hist[i] = 0u;
    if (t == 0) n_cand = 0;
    __syncthreads();

    // ---- load 3000 logits (750 float4) -> monotone keys + histogram ----
    const float4* logit4 =
        (const float4*)(cls + (size_t)(5 * BATCH + b) * QC + half * HALF);
    unsigned int key[NJ4 * 4];
#pragma unroll
    for (int v = 0; v < NJ4; v++) {
        const int idx4 = t + v * NT1;
        unsigned int m0 = 0u, m1 = 0u, m2 = 0u, m3 = 0u;
        if (idx4 < HV4) {
            float4 w = logit4[idx4];
            unsigned int u;
            u = __float_as_uint(w.x); m0 = (u & 0x80000000u) ? ~u : (u | 0x80000000u);
            u = __float_as_uint(w.y); m1 = (u & 0x80000000u) ? ~u : (u | 0x80000000u);
            u = __float_as_uint(w.z); m2 = (u & 0x80000000u) ? ~u : (u | 0x80000000u);
            u = __float_as_uint(w.w); m3 = (u & 0x80000000u) ? ~u : (u | 0x80000000u);
            atomicAdd(&hist[m0 >> 20], 1u);
            atomicAdd(&hist[m1 >> 20], 1u);
            atomicAdd(&hist[m2 >> 20], 1u);
            atomicAdd(&hist[m3 >> 20], 1u);
        }
        key[v * 4 + 0] = m0; key[v * 4 + 1] = m1;
        key[v * 4 + 2] = m2; key[v * 4 + 3] = m3;
    }
    __syncthreads();

    // ---- suffix scan (descending bins) for local top-100 cutoff ----
    const int bin_hi = NBINS - 1 - BPT * t;
    unsigned int ssum = 0u;
#pragma unroll
    for (int k = 0; k < BPT; k++) ssum += hist[bin_hi - k];

    unsigned int inc = ssum;
#pragma unroll
    for (int off = 1; off < 32; off <<= 1) {
        unsigned int v = __shfl_up_sync(0xFFFFFFFFu, inc, off);
        if (lane >= off) inc += v;
    }
    if (lane == 31) warp_tot[wid] = inc;
    __syncthreads();
    unsigned int woff = 0u;
#pragma unroll
    for (int i = 0; i < NT1 / 32; i++) woff += (i < wid) ? warp_tot[i] : 0u;
    const unsigned int excl = woff + inc - ssum;

    if (excl < TOPK && excl + ssum >= TOPK) {       // exactly one thread
        unsigned int acc = excl;
        int bc = bin_hi;
#pragma unroll
        for (int k = 0; k < BPT; k++) {
            acc += hist[bin_hi - k];
            if (acc >= TOPK) { bc = bin_hi - k; break; }
        }
        sh_bcut = bc;
    }
    __syncthreads();
    const unsigned int keycut = ((unsigned int)sh_bcut) << 20;

    // ---- warp-aggregated collect into smem ----
#pragma unroll
    for (int v = 0; v < NJ4; v++) {
        const int idx4 = t + v * NT1;
#pragma unroll
        for (int c = 0; c < 4; c++) {
            const unsigned int k = key[v * 4 + c];
            const bool pred = (k >= keycut) && (k != 0u);
            const unsigned int mask = __ballot_sync(0xFFFFFFFFu, pred);
            if (mask) {
                int base;
                if (lane == 0) base = atomicAdd(&n_cand, __popc(mask));
                base = __shfl_sync(0xFFFFFFFFu, base, 0);
                if (pred) {
                    int p = base + __popc(mask & ((1u << lane) - 1u));
                    if (p < HCAP) {
                        // global index within the batch
                        unsigned int gidx = (unsigned int)(half * HALF + idx4 * 4 + c);
                        cand[p] = ((unsigned long long)k << 32) |
                                  (unsigned int)(0xFFFFFFFFu - gidx);
                    }
                }
            }
        }
    }
    __syncthreads();

    // ---- coalesced write-out ----
    const int C = (n_cand < HCAP) ? n_cand : HCAP;
    for (int i = t; i < C; i += NT1) g_cand[bid][i] = cand[i];
    if (t == 0) g_cnt[bid] = C;
}

// ---------------- Kernel 2: merge, rank, decode, gather ----------------
__global__ __launch_bounds__(NT2, 2)
void k2_decode(const float* __restrict__ bbox,
               const float* __restrict__ pts,
               float* __restrict__ out)
{
    __shared__ unsigned long long cand[CAND_CAP];     // 8 KB

    const int b = blockIdx.x;
    const int t = threadIdx.x;

    const int n0 = g_cnt[b * 2];
    const int n1 = g_cnt[b * 2 + 1];
    for (int i = t; i < n0; i += NT2) cand[i]      = g_cand[b * 2][i];
    for (int i = t; i < n1; i += NT2) cand[n0 + i] = g_cand[b * 2 + 1][i];
    __syncthreads();
    const int C = n0 + n1;                            // <= 1024

    const float*  bbp = bbox + (size_t)(5 * BATCH + b) * NQ * 4;
    const float4* pp4 = (const float4*)(pts + (size_t)(5 * BATCH + b) * NQ * NP * 2);
    float4*       op4 = (float4*)(out + OFF_PTS + (size_t)b * TOPK * NP * 2);

    for (int i = t; i < C; i += NT2) {
        const unsigned long long me = cand[i];
        int rank = 0;
        int jj = 0;
        for (; jj + 4 <= C; jj += 4) {
            rank += (cand[jj]     > me);
            rank += (cand[jj + 1] > me);
            rank += (cand[jj + 2] > me);
            rank += (cand[jj + 3] > me);
        }
        for (; jj < C; jj++) rank += (cand[jj] > me);

        if (rank < TOPK) {
            unsigned int mono = (unsigned int)(me >> 32);
            unsigned int u = (mono & 0x80000000u) ? (mono ^ 0x80000000u) : ~mono;
            float f = __uint_as_float(u);
            float score = 1.0f / (1.0f + __expf(-f));
            int   g   = (int)(0xFFFFFFFFu - (unsigned int)me);
            int   bi  = g / NC;
            int   lab = g - bi * NC;

            float4 bv = *(const float4*)(bbp + (size_t)bi * 4);
            float x1 = (bv.x - 0.5f * bv.z) * 30.0f - 15.0f;
            float y1 = (bv.y - 0.5f * bv.w) * 60.0f - 30.0f;
            float x2 = (bv.x + 0.5f * bv.z) * 30.0f - 15.0f;
            float y2 = (bv.y + 0.5f * bv.w) * 60.0f - 30.0f;

            bool mk = (x1 >= -20.0f) && (y1 >= -35.0f) && (x2 >= -20.0f) && (y2 >= -35.0f) &&
                      (x1 <=  20.0f) && (y1 <=  35.0f) && (x2 <=  20.0f) && (y2 <=  35.0f);

            if (!mk) { x1 = y1 = x2 = y2 = 0.0f; }
            float* ob = out + OFF_BOXES + (size_t)(b * TOPK + rank) * 4;
            ob[0] = x1; ob[1] = y1; ob[2] = x2; ob[3] = y2;
            out[OFF_SCORES + b * TOPK + rank] = mk ? score : 0.0f;
            out[OFF_LABELS + b * TOPK + rank] = mk ? (float)lab : -1.0f;
            out[OFF_MASK   + b * TOPK + rank] = mk ? 1.0f : 0.0f;

            const float4* src = pp4 + (size_t)bi * NPQ;
            float4*       dst = op4 + (size_t)rank * NPQ;
            if (mk) {
#pragma unroll
                for (int q = 0; q < NPQ; q++) {
                    float4 r = src[q];
                    r.x = r.x * 30.0f - 15.0f;
                    r.y = r.y * 60.0f - 30.0f;
                    r.z = r.z * 30.0f - 15.0f;
                    r.w = r.w * 60.0f - 30.0f;
                    dst[q] = r;
                }
            } else {
                float4 z = make_float4(0.0f, 0.0f, 0.0f, 0.0f);
#pragma unroll
                for (int q = 0; q < NPQ; q++) dst[q] = z;
            }
        }
    }
}

extern "C" void kernel_launch(void* const* d_in, const int* in_sizes, int n_in,
                              void* d_out, int out_size)
{
    const float* cls = nullptr;
    const float* bb  = nullptr;
    const float* pt  = nullptr;
    for (int i = 0; i < n_in; i++) {
        if      (in_sizes[i] == 4608000)  cls = (const float*)d_in[i];
        else if (in_sizes[i] == 6144000)  bb  = (const float*)d_in[i];
        else if (in_sizes[i] == 61440000) pt  = (const float*)d_in[i];
    }
    if (!cls && n_in > 0) cls = (const float*)d_in[0];
    if (!bb  && n_in > 1) bb  = (const float*)d_in[1];
    if (!pt  && n_in > 2) pt  = (const float*)d_in[2];

    k1_select<<<BATCH * 2, NT1>>>(cls);
    k2_decode<<<BATCH, NT2>>>(bb, pt, (float*)d_out);
    (void)out_size;
}

// round 7
// speedup vs baseline: 1.5761x; 1.5761x over previous
#include <cuda_runtime.h>
#include <stdint.h>

#define BATCH 128
#define NQ    2000
#define NC    3
#define QC    6000
#define NV4   1500          // QC/4
#define TOPK  100
#define NP    20
#define NPQ   (NP * 2 / 4)  // 10 float4 per selection
#define NT    512
#define NJ4   3             // ceil(NV4/NT)
#define NBINS 4096
#define BPT   8             // NBINS/NT
#define CAND_CAP 1024

// Output layout (float32, reference tuple order, flattened):
#define OFF_BOXES  0
#define OFF_SCORES 51200
#define OFF_LABELS 64000
#define OFF_PTS    76800
#define OFF_MASK   588800

__global__ __launch_bounds__(NT, 1)
void maptr_post_kernel(const float* __restrict__ cls,
                       const float* __restrict__ bbox,
                       const float* __restrict__ pts,
                       float* __restrict__ out)
{
    __shared__ unsigned int       hist[NBINS];        // 16 KB
    __shared__ unsigned long long cand[CAND_CAP];     // 8 KB
    __shared__ int                n_cand;
    __shared__ unsigned int       warp_tot[NT / 32];
    __shared__ int                sh_bcut;

    const int b    = blockIdx.x;
    const int t    = threadIdx.x;
    const int wid  = t >> 5;
    const int lane = t & 31;

    // ---- issue global loads FIRST so DRAM latency hides behind hist init ----
    const float4* logit4 = (const float4*)(cls + (size_t)(5 * BATCH + b) * QC);
    float4 w[NJ4];
    bool   wv[NJ4];
#pragma unroll
    for (int v = 0; v < NJ4; v++) {
        const int idx4 = t + v * NT;
        wv[v] = (idx4 < NV4);
        w[v] = wv[v] ? logit4[idx4] : make_float4(0.f, 0.f, 0.f, 0.f);
    }

    // ---- histogram init (overlaps in-flight loads) ----
#pragma unroll
    for (int i = 0; i < NBINS / NT; i++) hist[t + i * NT] = 0u;
    if (t == 0) n_cand = 0;
    __syncthreads();

    // ---- monotone keys + 12-bit histogram ----
    unsigned int key[NJ4 * 4];
#pragma unroll
    for (int v = 0; v < NJ4; v++) {
        unsigned int m0 = 0u, m1 = 0u, m2 = 0u, m3 = 0u;
        if (wv[v]) {
            unsigned int u;
            u = __float_as_uint(w[v].x); m0 = (u & 0x80000000u) ? ~u : (u | 0x80000000u);
            u = __float_as_uint(w[v].y); m1 = (u & 0x80000000u) ? ~u : (u | 0x80000000u);
            u = __float_as_uint(w[v].z); m2 = (u & 0x80000000u) ? ~u : (u | 0x80000000u);
            u = __float_as_uint(w[v].w); m3 = (u & 0x80000000u) ? ~u : (u | 0x80000000u);
            atomicAdd(&hist[m0 >> 20], 1u);
            atomicAdd(&hist[m1 >> 20], 1u);
            atomicAdd(&hist[m2 >> 20], 1u);
            atomicAdd(&hist[m3 >> 20], 1u);
        }
        key[v * 4 + 0] = m0; key[v * 4 + 1] = m1;
        key[v * 4 + 2] = m2; key[v * 4 + 3] = m3;
    }
    __syncthreads();

    // ---- suffix scan (descending bins) to find cutoff bin ----
    const int bin_hi = NBINS - 1 - BPT * t;
    unsigned int ssum = 0u;
#pragma unroll
    for (int k = 0; k < BPT; k++) ssum += hist[bin_hi - k];

    unsigned int inc = ssum;
#pragma unroll
    for (int off = 1; off < 32; off <<= 1) {
        unsigned int v = __shfl_up_sync(0xFFFFFFFFu, inc, off);
        if (lane >= off) inc += v;
    }
    if (lane == 31) warp_tot[wid] = inc;
    __syncthreads();
    unsigned int woff = 0u;
    for (int i = 0; i < wid; i++) woff += warp_tot[i];
    const unsigned int excl = woff + inc - ssum;

    if (excl < TOPK && excl + ssum >= TOPK) {      // exactly one thread
        unsigned int acc = excl;
        int bc = bin_hi;
#pragma unroll
        for (int k = 0; k < BPT; k++) {
            acc += hist[bin_hi - k];
            if (acc >= TOPK) { bc = bin_hi - k; break; }
        }
        sh_bcut = bc;
    }
    __syncthreads();
    const unsigned int keycut = ((unsigned int)sh_bcut) << 20;

    // ---- pass 2: warp-aggregated candidate collection ----
#pragma unroll
    for (int v = 0; v < NJ4; v++) {
        const int idx4 = t + v * NT;
#pragma unroll
        for (int c = 0; c < 4; c++) {
            const unsigned int k = key[v * 4 + c];
            const bool pred = (k >= keycut) && (k != 0u);
            const unsigned int mask = __ballot_sync(0xFFFFFFFFu, pred);
            if (mask) {
                int base;
                if (lane == 0) base = atomicAdd(&n_cand, __popc(mask));
                base = __shfl_sync(0xFFFFFFFFu, base, 0);
                if (pred) {
                    int p = base + __popc(mask & ((1u << lane) - 1u));
                    if (p < CAND_CAP)
                        cand[p] = ((unsigned long long)k << 32) |
                                  (unsigned int)(0xFFFFFFFFu - (unsigned int)(idx4 * 4 + c));
                }
            }
        }
    }
    __syncthreads();
    const int C = (n_cand < CAND_CAP) ? n_cand : CAND_CAP;

    // ---- exact rank among candidates; rank<TOPK decodes + gathers ----
    const float*  bbp = bbox + (size_t)(5 * BATCH + b) * NQ * 4;
    const float4* pp4 = (const float4*)(pts + (size_t)(5 * BATCH + b) * NQ * NP * 2);
    float4*       op4 = (float4*)(out + OFF_PTS + (size_t)b * TOPK * NP * 2);

    for (int i = t; i < C; i += NT) {
        const unsigned long long me = cand[i];
        int rank = 0;
        int jj = 0;
        for (; jj + 4 <= C; jj += 4) {
            rank += (cand[jj]     > me);
            rank += (cand[jj + 1] > me);
            rank += (cand[jj + 2] > me);
            rank += (cand[jj + 3] > me);
        }
        for (; jj < C; jj++) rank += (cand[jj] > me);

        if (rank < TOPK) {
            const int g  = (int)(0xFFFFFFFFu - (unsigned int)me);
            const int bi = g / NC;
            const int lab = g - bi * NC;

            // issue ALL gather loads back-to-back (1 bbox + 10 pts float4):
            // one overlapped DRAM latency episode instead of two serial ones
            float4 bv = *(const float4*)(bbp + (size_t)bi * 4);
            const float4* src = pp4 + (size_t)bi * NPQ;
            float4 p[NPQ];
#pragma unroll
            for (int q = 0; q < NPQ; q++) p[q] = src[q];

            unsigned int mono = (unsigned int)(me >> 32);
            unsigned int u = (mono & 0x80000000u) ? (mono ^ 0x80000000u) : ~mono;
            float f = __uint_as_float(u);
            float score = 1.0f / (1.0f + __expf(-f));

            float x1 = (bv.x - 0.5f * bv.z) * 30.0f - 15.0f;
            float y1 = (bv.y - 0.5f * bv.w) * 60.0f - 30.0f;
            float x2 = (bv.x + 0.5f * bv.z) * 30.0f - 15.0f;
            float y2 = (bv.y + 0.5f * bv.w) * 60.0f - 30.0f;

            const bool mk =
                (x1 >= -20.0f) && (y1 >= -35.0f) && (x2 >= -20.0f) && (y2 >= -35.0f) &&
                (x1 <=  20.0f) && (y1 <=  35.0f) && (x2 <=  20.0f) && (y2 <=  35.0f);
            const float sel = mk ? 1.0f : 0.0f;

            float* ob = out + OFF_BOXES + (size_t)(b * TOPK + rank) * 4;
            ob[0] = x1 * sel; ob[1] = y1 * sel; ob[2] = x2 * sel; ob[3] = y2 * sel;
            out[OFF_SCORES + b * TOPK + rank] = score * sel;
            out[OFF_LABELS + b * TOPK + rank] = mk ? (float)lab : -1.0f;
            out[OFF_MASK   + b * TOPK + rank] = sel;

            float4* dst = op4 + (size_t)rank * NPQ;
#pragma unroll
            for (int q = 0; q < NPQ; q++) {
                float4 r = p[q];
                r.x = mk ? (r.x * 30.0f - 15.0f) : 0.0f;
                r.y = mk ? (r.y * 60.0f - 30.0f) : 0.0f;
                r.z = mk ? (r.z * 30.0f - 15.0f) : 0.0f;
                r.w = mk ? (r.w * 60.0f - 30.0f) : 0.0f;
                dst[q] = r;
            }
        }
    }
}

extern "C" void kernel_launch(void* const* d_in, const int* in_sizes, int n_in,
                              void* d_out, int out_size)
{
    const float* cls = nullptr;
    const float* bb  = nullptr;
    const float* pt  = nullptr;
    for (int i = 0; i < n_in; i++) {
        if      (in_sizes[i] == 4608000)  cls = (const float*)d_in[i];
        else if (in_sizes[i] == 6144000)  bb  = (const float*)d_in[i];
        else if (in_sizes[i] == 61440000) pt  = (const float*)d_in[i];
    }
    if (!cls && n_in > 0) cls = (const float*)d_in[0];
    if (!bb  && n_in > 1) bb  = (const float*)d_in[1];
    if (!pt  && n_in > 2) pt  = (const float*)d_in[2];

    maptr_post_kernel<<<BATCH, NT>>>(cls, bb, pt, (float*)d_out);
    (void)out_size;
}